// round 1
// baseline (speedup 1.0000x reference)
#include <cuda_runtime.h>
#include <cuda_bf16.h>
#include <math.h>

// ---------------------------------------------------------------------------
// GCN2: fc1 -> 3x(GCN2Conv + BN + ReLU) -> fc2 on a 50k-node / 800k-edge graph
// Strategy: CSR build (histogram+scan+scatter) once per launch, gather-based
// SpMM (no float atomics), fp32 tiled GEMMs, fused epilogues.
// ---------------------------------------------------------------------------

#define N_NODES 50000
#define E_EDGES 800000
#define IN_DIM  256
#define H_DIM   96
#define OUT_DIM 40

// ---- scratch (device globals: allocation-free rule) -----------------------
__device__ float g_dinv[N_NODES];
__device__ int   g_cnt[N_NODES];
__device__ int   g_fill[N_NODES];
__device__ int   g_start[N_NODES + 1];
__device__ int   g_src[E_EDGES];
__device__ float g_x0[N_NODES * H_DIM];   // fc1 output (initial residual)
__device__ float g_xs[N_NODES * H_DIM];   // dinv-prescaled current features
__device__ float g_hp[N_NODES * H_DIM];   // post-aggregation h
__device__ float g_h2[N_NODES * H_DIM];   // post identity-mapping h
__device__ float g_xcur[N_NODES * H_DIM]; // post BN+ReLU
__device__ float g_sum[H_DIM];
__device__ float g_sumsq[H_DIM];
__device__ float g_scale[H_DIM];
__device__ float g_shift[H_DIM];
__device__ int   g_is64;

// ---------------------------------------------------------------------------
// 0) dtype detection: int64 edge_index has zero high words at odd i32 slots
// ---------------------------------------------------------------------------
__global__ void detect_idx_kernel(const int* __restrict__ idx, int n_i32) {
    __shared__ int nz;
    if (threadIdx.x == 0) nz = 0;
    __syncthreads();
    int found = 0;
    for (int it = 0; it < 8; it++) {
        int p = 2 * (int)threadIdx.x + 1 + it * 1024;  // odd positions
        if (p < n_i32 && idx[p] != 0) found = 1;
    }
    if (found) atomicOr(&nz, 1);
    __syncthreads();
    if (threadIdx.x == 0) g_is64 = (nz == 0) ? 1 : 0;
}

__device__ __forceinline__ int load_row(const int* idx, int e) {
    return g_is64 ? idx[2 * e] : idx[e];           // little-endian low word
}
__device__ __forceinline__ int load_col(const int* idx, int e, int E) {
    return g_is64 ? idx[2 * (E + e)] : idx[E + e];
}

// ---------------------------------------------------------------------------
// 1) CSR build
// ---------------------------------------------------------------------------
__global__ void zero_counts_kernel(int N) {
    int i = blockIdx.x * blockDim.x + threadIdx.x;
    if (i < N) { g_cnt[i] = 0; g_fill[i] = 0; }
}

__global__ void count_edges_kernel(const int* __restrict__ idx, int E) {
    int e = blockIdx.x * blockDim.x + threadIdx.x;
    if (e < E) atomicAdd(&g_cnt[load_col(idx, e, E)], 1);
}

// single-block scan over N counts; also computes dinv = rsqrt(deg+1)
__global__ void scan_kernel(int N) {
    __shared__ int sm[1024];
    int tid = threadIdx.x;
    const int CH = (N + 1023) >> 10;
    int base = tid * CH;
    int s = 0;
    for (int j = 0; j < CH; j++) {
        int i = base + j;
        if (i < N) s += g_cnt[i];
    }
    sm[tid] = s;
    __syncthreads();
    for (int off = 1; off < 1024; off <<= 1) {
        int v = (tid >= off) ? sm[tid - off] : 0;
        __syncthreads();
        sm[tid] += v;
        __syncthreads();
    }
    int run = (tid > 0) ? sm[tid - 1] : 0;
    for (int j = 0; j < CH; j++) {
        int i = base + j;
        if (i < N) {
            g_start[i] = run;
            int c = g_cnt[i];
            run += c;
            g_dinv[i] = rsqrtf((float)(c + 1));  // +1 self-loop; deg>0 always
        }
    }
    if (tid == 1023) g_start[N] = sm[1023];
}

__global__ void scatter_edges_kernel(const int* __restrict__ idx, int E) {
    int e = blockIdx.x * blockDim.x + threadIdx.x;
    if (e < E) {
        int r = load_row(idx, e);
        int c = load_col(idx, e, E);
        int p = g_start[c] + atomicAdd(&g_fill[c], 1);
        g_src[p] = r;
    }
}

// ---------------------------------------------------------------------------
// 2) tiled GEMM, N fixed = 96.  C = A[M,K] @ B[K,96]  (+bias/blend/relu)
//    BM=64 BN=96 BK=16, 256 threads, each thread 8x3 outputs.
// ---------------------------------------------------------------------------
__global__ void __launch_bounds__(256) gemm96_kernel(
    const float* __restrict__ A, const float* __restrict__ B,
    const float* __restrict__ bias, const float* __restrict__ blend,
    float ba, float bb, int do_relu, int write_xs,
    float* __restrict__ out, int M, int K)
{
    __shared__ float As[16][65];
    __shared__ float Bs[16][96];
    int tid = threadIdx.x;
    int tx = tid & 31, ty = tid >> 5;
    int bm = blockIdx.x * 64;

    float acc[8][3];
#pragma unroll
    for (int i = 0; i < 8; i++)
#pragma unroll
        for (int j = 0; j < 3; j++) acc[i][j] = 0.f;

    int arow = tid >> 2;          // 0..63
    int akq  = (tid & 3) * 4;     // 0,4,8,12

    for (int k0 = 0; k0 < K; k0 += 16) {
        float4 av = make_float4(0.f, 0.f, 0.f, 0.f);
        int gr = bm + arow;
        if (gr < M) av = *(const float4*)(A + (size_t)gr * K + k0 + akq);
        As[akq + 0][arow] = av.x;
        As[akq + 1][arow] = av.y;
        As[akq + 2][arow] = av.z;
        As[akq + 3][arow] = av.w;
#pragma unroll
        for (int j = 0; j < 6; j++) {
            int idx = tid + j * 256;
            int bk = idx / 96, bn = idx - bk * 96;
            Bs[bk][bn] = B[(size_t)(k0 + bk) * 96 + bn];
        }
        __syncthreads();
#pragma unroll
        for (int k = 0; k < 16; k++) {
            float b0 = Bs[k][tx], b1 = Bs[k][tx + 32], b2 = Bs[k][tx + 64];
#pragma unroll
            for (int i = 0; i < 8; i++) {
                float a = As[k][ty * 8 + i];
                acc[i][0] += a * b0;
                acc[i][1] += a * b1;
                acc[i][2] += a * b2;
            }
        }
        __syncthreads();
    }

#pragma unroll
    for (int i = 0; i < 8; i++) {
        int row = bm + ty * 8 + i;
        if (row >= M) continue;
        float dv = write_xs ? g_dinv[row] : 0.f;
#pragma unroll
        for (int j = 0; j < 3; j++) {
            int col = tx + j * 32;
            float v = acc[i][j];
            if (bias)  v += bias[col];
            if (blend) v = ba * blend[(size_t)row * 96 + col] + bb * v;
            if (do_relu) v = fmaxf(v, 0.f);
            size_t o = (size_t)row * 96 + col;
            out[o] = v;
            if (write_xs) g_xs[o] = dv * v;
        }
    }
}

// ---------------------------------------------------------------------------
// 3) gather SpMM: one warp per destination node, 3 features/lane.
//    hp[c] = 0.9 * dinv[c] * (xs[c] + sum_{src} xs[src]) + 0.1 * x0[c]
// ---------------------------------------------------------------------------
__global__ void __launch_bounds__(256) gather_kernel(
    const float* __restrict__ xs, const float* __restrict__ x0,
    float* __restrict__ hp, int N)
{
    int warp = (blockIdx.x * blockDim.x + threadIdx.x) >> 5;
    int lane = threadIdx.x & 31;
    if (warp >= N) return;
    int c = warp;
    int s0 = g_start[c], s1 = g_start[c + 1];
    size_t base = (size_t)c * 96 + lane;
    float a0 = xs[base], a1 = xs[base + 32], a2 = xs[base + 64];
    int j = s0;
    for (; j + 1 < s1; j += 2) {          // unroll 2 for MLP
        int sA = g_src[j], sB = g_src[j + 1];
        const float* pA = xs + (size_t)sA * 96;
        const float* pB = xs + (size_t)sB * 96;
        a0 += pA[lane]      + pB[lane];
        a1 += pA[lane + 32] + pB[lane + 32];
        a2 += pA[lane + 64] + pB[lane + 64];
    }
    if (j < s1) {
        const float* p = xs + (size_t)g_src[j] * 96;
        a0 += p[lane]; a1 += p[lane + 32]; a2 += p[lane + 64];
    }
    float w = 0.9f * g_dinv[c];
    hp[base]      = w * a0 + 0.1f * x0[base];
    hp[base + 32] = w * a1 + 0.1f * x0[base + 32];
    hp[base + 64] = w * a2 + 0.1f * x0[base + 64];
}

// ---------------------------------------------------------------------------
// 4) BatchNorm over node dim
// ---------------------------------------------------------------------------
__global__ void zero_stats_kernel() {
    int h = threadIdx.x;
    if (h < H_DIM) { g_sum[h] = 0.f; g_sumsq[h] = 0.f; }
}

__global__ void __launch_bounds__(384) bn_stats_kernel(const float* __restrict__ h2, int N) {
    __shared__ float ssum[4][96];
    __shared__ float ssq[4][96];
    int h  = threadIdx.x % 96;
    int ty = threadIdx.x / 96;
    float s = 0.f, q = 0.f;
    for (int r = blockIdx.x * 4 + ty; r < N; r += gridDim.x * 4) {
        float v = h2[(size_t)r * 96 + h];
        s += v; q += v * v;
    }
    ssum[ty][h] = s; ssq[ty][h] = q;
    __syncthreads();
    if (ty == 0) {
        s = ssum[0][h] + ssum[1][h] + ssum[2][h] + ssum[3][h];
        q = ssq[0][h] + ssq[1][h] + ssq[2][h] + ssq[3][h];
        atomicAdd(&g_sum[h], s);
        atomicAdd(&g_sumsq[h], q);
    }
}

__global__ void bn_final_kernel(const float* __restrict__ gamma,
                                const float* __restrict__ beta, int N) {
    int h = threadIdx.x;
    if (h < H_DIM) {
        float m  = g_sum[h] / (float)N;
        float vr = g_sumsq[h] / (float)N - m * m;
        float rs = rsqrtf(vr + 1e-5f);
        float sc = gamma[h] * rs;
        g_scale[h] = sc;
        g_shift[h] = beta[h] - m * sc;
    }
}

// BN apply + relu, also prescale for next gather: xs = dinv * x
__global__ void __launch_bounds__(256) bn_apply_kernel(
    const float* __restrict__ h2, float* __restrict__ x, int N)
{
    int i = blockIdx.x * blockDim.x + threadIdx.x;
    int total = N * 96;
    if (i < total) {
        int h = i % 96;
        int r = i / 96;
        float v = g_scale[h] * h2[i] + g_shift[h];
        v = fmaxf(v, 0.f);
        x[i] = v;
        g_xs[i] = g_dinv[r] * v;
    }
}

// ---------------------------------------------------------------------------
// 5) fc2: out[M,40] = A[M,96] @ W[96,40] + b   (W held in smem)
// ---------------------------------------------------------------------------
__global__ void __launch_bounds__(320) fc2_kernel(
    const float* __restrict__ A, const float* __restrict__ W,
    const float* __restrict__ bias, float* __restrict__ out, int M)
{
    __shared__ float Ws[96 * 40];
    __shared__ float bs[40];
    __shared__ float Asm[8][96];
    int tid = threadIdx.x;
    for (int i = tid; i < 96 * 40; i += 320) Ws[i] = W[i];
    if (tid < 40) bs[tid] = bias[tid];
    int tx = tid % 40, ty = tid / 40;
    for (int r0 = blockIdx.x * 8; r0 < M; r0 += gridDim.x * 8) {
        __syncthreads();
        for (int i = tid; i < 768; i += 320) {
            int r = i / 96, k = i - r * 96;
            Asm[r][k] = (r0 + r < M) ? A[(size_t)(r0 + r) * 96 + k] : 0.f;
        }
        __syncthreads();
        float acc = bs[tx];
#pragma unroll
        for (int k = 0; k < 96; k++) acc += Asm[ty][k] * Ws[k * 40 + tx];
        if (r0 + ty < M) out[(size_t)(r0 + ty) * 40 + tx] = acc;
    }
}

// ---------------------------------------------------------------------------
// launch
// ---------------------------------------------------------------------------
extern "C" void kernel_launch(void* const* d_in, const int* in_sizes, int n_in,
                              void* d_out, int out_size) {
    const float* x_in    = (const float*)d_in[0];
    const int*   eidx    = (const int*)d_in[1];
    const float* fc1_w   = (const float*)d_in[2];
    const float* fc1_b   = (const float*)d_in[3];
    const float* conv_w  = (const float*)d_in[4];
    const float* bn_g    = (const float*)d_in[5];
    const float* bn_b    = (const float*)d_in[6];
    const float* fc2_w   = (const float*)d_in[7];
    const float* fc2_b   = (const float*)d_in[8];
    float* out = (float*)d_out;

    int N = in_sizes[0] / IN_DIM;   // 50000
    int E = in_sizes[1] / 2;        // 800000
    if (N > N_NODES) N = N_NODES;
    if (E > E_EDGES) E = E_EDGES;

    // resolve device-symbol addresses (host side, no allocation)
    float *p_x0, *p_xs, *p_hp, *p_h2, *p_x;
    cudaGetSymbolAddress((void**)&p_x0, g_x0);
    cudaGetSymbolAddress((void**)&p_xs, g_xs);
    cudaGetSymbolAddress((void**)&p_hp, g_hp);
    cudaGetSymbolAddress((void**)&p_h2, g_h2);
    cudaGetSymbolAddress((void**)&p_x,  g_xcur);

    // ---- graph preprocessing (CSR + dinv) ----
    detect_idx_kernel<<<1, 512>>>(eidx, 2 * E);
    zero_counts_kernel<<<(N + 255) / 256, 256>>>(N);
    count_edges_kernel<<<(E + 255) / 256, 256>>>(eidx, E);
    scan_kernel<<<1, 1024>>>(N);
    scatter_edges_kernel<<<(E + 255) / 256, 256>>>(eidx, E);

    // ---- fc1 + relu (writes x0 and xs = dinv*x0) ----
    gemm96_kernel<<<(N + 63) / 64, 256>>>(
        x_in, fc1_w, fc1_b, nullptr, 0.f, 0.f, /*relu=*/1, /*write_xs=*/1,
        p_x0, N, IN_DIM);

    int gather_grid = (N * 32 + 255) / 256;
    int ew_grid = (N * 96 + 255) / 256;

    for (int i = 0; i < 3; i++) {
        float beta = logf(0.5f / (float)(i + 1) + 1.0f);
        // gather: hp = 0.9*agg + 0.1*x0
        gather_kernel<<<gather_grid, 256>>>(p_xs, p_x0, p_hp, N);
        zero_stats_kernel<<<1, 96>>>();
        // identity mapping: h2 = (1-beta)*hp + beta*(hp @ W_i)
        gemm96_kernel<<<(N + 63) / 64, 256>>>(
            p_hp, conv_w + (size_t)i * H_DIM * H_DIM, nullptr, p_hp,
            1.f - beta, beta, /*relu=*/0, /*write_xs=*/0, p_h2, N, H_DIM);
        // batchnorm + relu (+ prescale xs for next layer)
        bn_stats_kernel<<<128, 384>>>(p_h2, N);
        bn_final_kernel<<<1, 96>>>(bn_g + i * H_DIM, bn_b + i * H_DIM, N);
        bn_apply_kernel<<<ew_grid, 256>>>(p_h2, p_x, N);
    }

    // ---- fc2 ----
    fc2_kernel<<<512, 320>>>(p_x, fc2_w, fc2_b, out, N);
}

// round 2
// speedup vs baseline: 1.3694x; 1.3694x over previous
#include <cuda_runtime.h>
#include <cuda_bf16.h>
#include <math.h>

// ---------------------------------------------------------------------------
// GCN2: fc1 -> 3x(GCN2Conv + BN + ReLU) -> fc2 on a 50k-node / 800k-edge graph
// R1 changes: parallel 3-phase scan (was 82us serial), BN stats fused into
// conv-GEMM epilogue, BN scale/shift computed per consumer block, last-layer
// BN+ReLU fused into fc2.
// ---------------------------------------------------------------------------

#define N_NODES 50000
#define E_EDGES 800000
#define IN_DIM  256
#define H_DIM   96
#define OUT_DIM 40
#define SCAN_NB_MAX 256   // ceil(N/256) = 196 for N=50000

// ---- scratch (device globals: allocation-free rule) -----------------------
__device__ float g_dinv[N_NODES];
__device__ int   g_cnt[N_NODES];
__device__ int   g_fill[N_NODES];
__device__ int   g_start[N_NODES + 1];
__device__ int   g_bsum[SCAN_NB_MAX];
__device__ int   g_boff[SCAN_NB_MAX];
__device__ int   g_src[E_EDGES];
__device__ float g_x0[N_NODES * H_DIM];   // fc1 output (initial residual)
__device__ float g_xs[N_NODES * H_DIM];   // dinv-prescaled current features
__device__ float g_hp[N_NODES * H_DIM];   // post-aggregation h
__device__ float g_h2[N_NODES * H_DIM];   // post identity-mapping h
__device__ float g_xcur[N_NODES * H_DIM]; // post BN+ReLU
__device__ float g_sum[3 * H_DIM];        // per-layer BN sums
__device__ float g_sumsq[3 * H_DIM];
__device__ int   g_is64;

// ---------------------------------------------------------------------------
// 0) dtype detection: int64 edge_index has zero high words at odd i32 slots
// ---------------------------------------------------------------------------
__global__ void detect_idx_kernel(const int* __restrict__ idx, int n_i32) {
    __shared__ int nz;
    if (threadIdx.x == 0) nz = 0;
    __syncthreads();
    int found = 0;
    for (int it = 0; it < 8; it++) {
        int p = 2 * (int)threadIdx.x + 1 + it * 1024;  // odd positions
        if (p < n_i32 && idx[p] != 0) found = 1;
    }
    if (found) atomicOr(&nz, 1);
    __syncthreads();
    if (threadIdx.x == 0) g_is64 = (nz == 0) ? 1 : 0;
}

__device__ __forceinline__ int load_row(const int* idx, int e) {
    return g_is64 ? idx[2 * e] : idx[e];           // little-endian low word
}
__device__ __forceinline__ int load_col(const int* idx, int e, int E) {
    return g_is64 ? idx[2 * (E + e)] : idx[E + e];
}

// ---------------------------------------------------------------------------
// 1) CSR build
// ---------------------------------------------------------------------------
__global__ void zero_all_kernel(int N) {
    int i = blockIdx.x * blockDim.x + threadIdx.x;
    if (i < N) { g_cnt[i] = 0; g_fill[i] = 0; }
    if (i < 3 * H_DIM) { g_sum[i] = 0.f; g_sumsq[i] = 0.f; }
}

__global__ void count_edges_kernel(const int* __restrict__ idx, int E) {
    int e = blockIdx.x * blockDim.x + threadIdx.x;
    if (e < E) atomicAdd(&g_cnt[load_col(idx, e, E)], 1);
}

// phase 1: block-local exclusive scan of counts (256/block), emit block sums.
// also computes dinv = rsqrt(deg+1).
__global__ void scan1_kernel(int N) {
    __shared__ int sm[256];
    int t = threadIdx.x;
    int i = blockIdx.x * 256 + t;
    int c = (i < N) ? g_cnt[i] : 0;
    if (i < N) g_dinv[i] = rsqrtf((float)(c + 1));
    sm[t] = c;
    __syncthreads();
    int acc = c;
#pragma unroll
    for (int off = 1; off < 256; off <<= 1) {
        int v = (t >= off) ? sm[t - off] : 0;
        __syncthreads();
        acc += v;
        sm[t] = acc;
        __syncthreads();
    }
    if (i < N) g_start[i] = acc - c;           // exclusive
    if (t == 255) g_bsum[blockIdx.x] = acc;    // block total
}

// phase 2: single-block scan of block sums -> block offsets; writes g_start[N]
__global__ void scan2_kernel(int NB, int N) {
    __shared__ int sm[SCAN_NB_MAX];
    int t = threadIdx.x;
    int v = (t < NB) ? g_bsum[t] : 0;
    sm[t] = v;
    __syncthreads();
    int acc = v;
#pragma unroll
    for (int off = 1; off < SCAN_NB_MAX; off <<= 1) {
        int u = (t >= off) ? sm[t - off] : 0;
        __syncthreads();
        acc += u;
        sm[t] = acc;
        __syncthreads();
    }
    if (t < NB) g_boff[t] = acc - v;           // exclusive
    if (t == NB - 1) g_start[N] = acc;         // grand total = E
}

// phase 3: add block offsets
__global__ void scan3_kernel(int N) {
    int i = blockIdx.x * 256 + threadIdx.x;
    if (i < N) g_start[i] += g_boff[blockIdx.x];
}

__global__ void scatter_edges_kernel(const int* __restrict__ idx, int E) {
    int e = blockIdx.x * blockDim.x + threadIdx.x;
    if (e < E) {
        int r = load_row(idx, e);
        int c = load_col(idx, e, E);
        int p = g_start[c] + atomicAdd(&g_fill[c], 1);
        g_src[p] = r;
    }
}

// ---------------------------------------------------------------------------
// 2) tiled GEMM, N fixed = 96.  C = A[M,K] @ B[K,96]  (+bias/blend/relu)
//    BM=64 BN=96 BK=16, 256 threads, each thread 8x3 outputs.
//    Optional: accumulate per-column BN stats of the output into g_sum/g_sumsq
// ---------------------------------------------------------------------------
__global__ void __launch_bounds__(256) gemm96_kernel(
    const float* __restrict__ A, const float* __restrict__ B,
    const float* __restrict__ bias, const float* __restrict__ blend,
    float ba, float bb, int do_relu, int write_xs, int stat_layer,
    float* __restrict__ out, int M, int K)
{
    __shared__ float As[16][65];
    __shared__ float Bs[16][96];
    __shared__ float RedS[8][96];
    __shared__ float RedQ[8][96];
    int tid = threadIdx.x;
    int tx = tid & 31, ty = tid >> 5;
    int bm = blockIdx.x * 64;

    float acc[8][3];
#pragma unroll
    for (int i = 0; i < 8; i++)
#pragma unroll
        for (int j = 0; j < 3; j++) acc[i][j] = 0.f;

    int arow = tid >> 2;          // 0..63
    int akq  = (tid & 3) * 4;     // 0,4,8,12

    for (int k0 = 0; k0 < K; k0 += 16) {
        float4 av = make_float4(0.f, 0.f, 0.f, 0.f);
        int gr = bm + arow;
        if (gr < M) av = *(const float4*)(A + (size_t)gr * K + k0 + akq);
        As[akq + 0][arow] = av.x;
        As[akq + 1][arow] = av.y;
        As[akq + 2][arow] = av.z;
        As[akq + 3][arow] = av.w;
#pragma unroll
        for (int j = 0; j < 6; j++) {
            int idx = tid + j * 256;
            int bk = idx / 96, bn = idx - bk * 96;
            Bs[bk][bn] = B[(size_t)(k0 + bk) * 96 + bn];
        }
        __syncthreads();
#pragma unroll
        for (int k = 0; k < 16; k++) {
            float b0 = Bs[k][tx], b1 = Bs[k][tx + 32], b2 = Bs[k][tx + 64];
#pragma unroll
            for (int i = 0; i < 8; i++) {
                float a = As[k][ty * 8 + i];
                acc[i][0] += a * b0;
                acc[i][1] += a * b1;
                acc[i][2] += a * b2;
            }
        }
        __syncthreads();
    }

    float s_c[3] = {0.f, 0.f, 0.f};
    float q_c[3] = {0.f, 0.f, 0.f};
#pragma unroll
    for (int i = 0; i < 8; i++) {
        int row = bm + ty * 8 + i;
        if (row >= M) continue;
        float dv = write_xs ? g_dinv[row] : 0.f;
#pragma unroll
        for (int j = 0; j < 3; j++) {
            int col = tx + j * 32;
            float v = acc[i][j];
            if (bias)  v += bias[col];
            if (blend) v = ba * blend[(size_t)row * 96 + col] + bb * v;
            if (do_relu) v = fmaxf(v, 0.f);
            size_t o = (size_t)row * 96 + col;
            out[o] = v;
            if (write_xs) g_xs[o] = dv * v;
            if (stat_layer >= 0) { s_c[j] += v; q_c[j] += v * v; }
        }
    }

    if (stat_layer >= 0) {
#pragma unroll
        for (int j = 0; j < 3; j++) {
            RedS[ty][tx + j * 32] = s_c[j];
            RedQ[ty][tx + j * 32] = q_c[j];
        }
        __syncthreads();
        if (ty == 0) {
#pragma unroll
            for (int j = 0; j < 3; j++) {
                int col = tx + j * 32;
                float s = 0.f, q = 0.f;
#pragma unroll
                for (int y = 0; y < 8; y++) { s += RedS[y][col]; q += RedQ[y][col]; }
                atomicAdd(&g_sum[stat_layer * H_DIM + col], s);
                atomicAdd(&g_sumsq[stat_layer * H_DIM + col], q);
            }
        }
    }
}

// ---------------------------------------------------------------------------
// 3) gather SpMM: one warp per destination node, 3 features/lane.
//    hp[c] = 0.9 * dinv[c] * (xs[c] + sum_{src} xs[src]) + 0.1 * x0[c]
// ---------------------------------------------------------------------------
__global__ void __launch_bounds__(256) gather_kernel(
    const float* __restrict__ xs, const float* __restrict__ x0,
    float* __restrict__ hp, int N)
{
    int warp = (blockIdx.x * blockDim.x + threadIdx.x) >> 5;
    int lane = threadIdx.x & 31;
    if (warp >= N) return;
    int c = warp;
    int s0 = g_start[c], s1 = g_start[c + 1];
    size_t base = (size_t)c * 96 + lane;
    float a0 = xs[base], a1 = xs[base + 32], a2 = xs[base + 64];
    int j = s0;
    for (; j + 1 < s1; j += 2) {          // unroll 2 for MLP
        int sA = g_src[j], sB = g_src[j + 1];
        const float* pA = xs + (size_t)sA * 96;
        const float* pB = xs + (size_t)sB * 96;
        a0 += pA[lane]      + pB[lane];
        a1 += pA[lane + 32] + pB[lane + 32];
        a2 += pA[lane + 64] + pB[lane + 64];
    }
    if (j < s1) {
        const float* p = xs + (size_t)g_src[j] * 96;
        a0 += p[lane]; a1 += p[lane + 32]; a2 += p[lane + 64];
    }
    float w = 0.9f * g_dinv[c];
    hp[base]      = w * a0 + 0.1f * x0[base];
    hp[base + 32] = w * a1 + 0.1f * x0[base + 32];
    hp[base + 64] = w * a2 + 0.1f * x0[base + 64];
}

// ---------------------------------------------------------------------------
// 4) BN apply + relu (+ prescale xs for next gather). scale/shift computed
//    per block from the globally accumulated stats (cheap: 96 rsqrt).
// ---------------------------------------------------------------------------
__global__ void __launch_bounds__(256) bn_apply_kernel(
    const float* __restrict__ h2, const float* __restrict__ gamma,
    const float* __restrict__ beta, int layer, float* __restrict__ x, int N)
{
    __shared__ float sc[96], sh[96];
    if (threadIdx.x < 96) {
        int h = threadIdx.x;
        float m  = g_sum[layer * H_DIM + h] / (float)N;
        float vr = g_sumsq[layer * H_DIM + h] / (float)N - m * m;
        float rs = rsqrtf(vr + 1e-5f);
        float s = gamma[h] * rs;
        sc[h] = s;
        sh[h] = beta[h] - m * s;
    }
    __syncthreads();
    int i = blockIdx.x * blockDim.x + threadIdx.x;
    int total = N * 96;
    if (i < total) {
        int h = i % 96;
        int r = i / 96;
        float v = sc[h] * h2[i] + sh[h];
        v = fmaxf(v, 0.f);
        x[i] = v;
        g_xs[i] = g_dinv[r] * v;
    }
}

// ---------------------------------------------------------------------------
// 5) fc2: out[M,40] = relu(BN(A))[M,96] @ W[96,40] + b   (BN fused for layer 2)
// ---------------------------------------------------------------------------
__global__ void __launch_bounds__(320) fc2_kernel(
    const float* __restrict__ A, const float* __restrict__ W,
    const float* __restrict__ bias, const float* __restrict__ gamma,
    const float* __restrict__ beta, int layer, float* __restrict__ out, int M)
{
    __shared__ float Ws[96 * 40];
    __shared__ float bs[40];
    __shared__ float Asm[8][96];
    __shared__ float sc[96], sh[96];
    int tid = threadIdx.x;
    for (int i = tid; i < 96 * 40; i += 320) Ws[i] = W[i];
    if (tid < 40) bs[tid] = bias[tid];
    if (tid < 96) {
        int h = tid;
        float m  = g_sum[layer * H_DIM + h] / (float)M;
        float vr = g_sumsq[layer * H_DIM + h] / (float)M - m * m;
        float rs = rsqrtf(vr + 1e-5f);
        float s = gamma[h] * rs;
        sc[h] = s;
        sh[h] = beta[h] - m * s;
    }
    int tx = tid % 40, ty = tid / 40;
    for (int r0 = blockIdx.x * 8; r0 < M; r0 += gridDim.x * 8) {
        __syncthreads();
        for (int i = tid; i < 768; i += 320) {
            int r = i / 96, k = i - r * 96;
            float v = (r0 + r < M) ? A[(size_t)(r0 + r) * 96 + k] : 0.f;
            v = fmaxf(sc[k] * v + sh[k], 0.f);   // BN + ReLU fused
            Asm[r][k] = v;
        }
        __syncthreads();
        float acc = bs[tx];
#pragma unroll
        for (int k = 0; k < 96; k++) acc += Asm[ty][k] * Ws[k * 40 + tx];
        if (r0 + ty < M) out[(size_t)(r0 + ty) * 40 + tx] = acc;
    }
}

// ---------------------------------------------------------------------------
// launch
// ---------------------------------------------------------------------------
extern "C" void kernel_launch(void* const* d_in, const int* in_sizes, int n_in,
                              void* d_out, int out_size) {
    const float* x_in    = (const float*)d_in[0];
    const int*   eidx    = (const int*)d_in[1];
    const float* fc1_w   = (const float*)d_in[2];
    const float* fc1_b   = (const float*)d_in[3];
    const float* conv_w  = (const float*)d_in[4];
    const float* bn_g    = (const float*)d_in[5];
    const float* bn_b    = (const float*)d_in[6];
    const float* fc2_w   = (const float*)d_in[7];
    const float* fc2_b   = (const float*)d_in[8];
    float* out = (float*)d_out;

    int N = in_sizes[0] / IN_DIM;   // 50000
    int E = in_sizes[1] / 2;        // 800000
    if (N > N_NODES) N = N_NODES;
    if (E > E_EDGES) E = E_EDGES;
    int NB = (N + 255) / 256;       // 196

    float *p_x0, *p_xs, *p_hp, *p_h2, *p_x;
    cudaGetSymbolAddress((void**)&p_x0, g_x0);
    cudaGetSymbolAddress((void**)&p_xs, g_xs);
    cudaGetSymbolAddress((void**)&p_hp, g_hp);
    cudaGetSymbolAddress((void**)&p_h2, g_h2);
    cudaGetSymbolAddress((void**)&p_x,  g_xcur);

    // ---- graph preprocessing (CSR + dinv) ----
    detect_idx_kernel<<<1, 512>>>(eidx, 2 * E);
    zero_all_kernel<<<NB, 256>>>(N);
    count_edges_kernel<<<(E + 255) / 256, 256>>>(eidx, E);
    scan1_kernel<<<NB, 256>>>(N);
    scan2_kernel<<<1, SCAN_NB_MAX>>>(NB, N);
    scan3_kernel<<<NB, 256>>>(N);
    scatter_edges_kernel<<<(E + 255) / 256, 256>>>(eidx, E);

    // ---- fc1 + relu (writes x0 and xs = dinv*x0) ----
    gemm96_kernel<<<(N + 63) / 64, 256>>>(
        x_in, fc1_w, fc1_b, nullptr, 0.f, 0.f, /*relu=*/1, /*write_xs=*/1,
        /*stat_layer=*/-1, p_x0, N, IN_DIM);

    int gather_grid = (N * 32 + 255) / 256;
    int ew_grid = (N * 96 + 255) / 256;

    for (int i = 0; i < 3; i++) {
        float beta = logf(0.5f / (float)(i + 1) + 1.0f);
        // gather: hp = 0.9*agg + 0.1*x0
        gather_kernel<<<gather_grid, 256>>>(p_xs, p_x0, p_hp, N);
        // identity mapping: h2 = (1-beta)*hp + beta*(hp @ W_i), BN stats fused
        gemm96_kernel<<<(N + 63) / 64, 256>>>(
            p_hp, conv_w + (size_t)i * H_DIM * H_DIM, nullptr, p_hp,
            1.f - beta, beta, /*relu=*/0, /*write_xs=*/0, /*stat_layer=*/i,
            p_h2, N, H_DIM);
        if (i < 2) {
            // batchnorm + relu (+ prescale xs for next layer)
            bn_apply_kernel<<<ew_grid, 256>>>(
                p_h2, bn_g + i * H_DIM, bn_b + i * H_DIM, i, p_x, N);
        }
    }

    // ---- fc2 with layer-2 BN+ReLU fused ----
    fc2_kernel<<<512, 320>>>(p_h2, fc2_w, fc2_b, bn_g + 2 * H_DIM,
                             bn_b + 2 * H_DIM, 2, out, N);
}

// round 3
// speedup vs baseline: 1.5313x; 1.1183x over previous
#include <cuda_runtime.h>
#include <cuda_bf16.h>
#include <math.h>
#include <mma.h>

using namespace nvcuda;

// ---------------------------------------------------------------------------
// GCN2: fc1 -> 3x(GCN2Conv + BN + ReLU) -> fc2 on a 50k-node / 800k-edge graph
// R2 changes: fc1/conv GEMMs moved to TF32 tensor cores (wmma m16n16k8) with
// fused epilogues (bias/blend/relu/BN-stats/xs-prescale) via smem staging.
// ---------------------------------------------------------------------------

#define N_NODES 50000
#define E_EDGES 800000
#define IN_DIM  256
#define H_DIM   96
#define OUT_DIM 40
#define SCAN_NB_MAX 256   // ceil(N/256) = 196 for N=50000

// ---- scratch (device globals: allocation-free rule) -----------------------
__device__ float g_dinv[N_NODES];
__device__ int   g_cnt[N_NODES];
__device__ int   g_fill[N_NODES];
__device__ int   g_start[N_NODES + 1];
__device__ int   g_bsum[SCAN_NB_MAX];
__device__ int   g_boff[SCAN_NB_MAX];
__device__ int   g_src[E_EDGES];
__device__ float g_x0[N_NODES * H_DIM];   // fc1 output (initial residual)
__device__ float g_xs[N_NODES * H_DIM];   // dinv-prescaled current features
__device__ float g_hp[N_NODES * H_DIM];   // post-aggregation h
__device__ float g_h2[N_NODES * H_DIM];   // post identity-mapping h
__device__ float g_xcur[N_NODES * H_DIM]; // post BN+ReLU
__device__ float g_sum[3 * H_DIM];        // per-layer BN sums
__device__ float g_sumsq[3 * H_DIM];
__device__ int   g_is64;

// ---------------------------------------------------------------------------
// 0) dtype detection: int64 edge_index has zero high words at odd i32 slots
// ---------------------------------------------------------------------------
__global__ void detect_idx_kernel(const int* __restrict__ idx, int n_i32) {
    __shared__ int nz;
    if (threadIdx.x == 0) nz = 0;
    __syncthreads();
    int found = 0;
    for (int it = 0; it < 8; it++) {
        int p = 2 * (int)threadIdx.x + 1 + it * 1024;  // odd positions
        if (p < n_i32 && idx[p] != 0) found = 1;
    }
    if (found) atomicOr(&nz, 1);
    __syncthreads();
    if (threadIdx.x == 0) g_is64 = (nz == 0) ? 1 : 0;
}

__device__ __forceinline__ int load_row(const int* idx, int e) {
    return g_is64 ? idx[2 * e] : idx[e];           // little-endian low word
}
__device__ __forceinline__ int load_col(const int* idx, int e, int E) {
    return g_is64 ? idx[2 * (E + e)] : idx[E + e];
}

// ---------------------------------------------------------------------------
// 1) CSR build
// ---------------------------------------------------------------------------
__global__ void zero_all_kernel(int N) {
    int i = blockIdx.x * blockDim.x + threadIdx.x;
    if (i < N) { g_cnt[i] = 0; g_fill[i] = 0; }
    if (i < 3 * H_DIM) { g_sum[i] = 0.f; g_sumsq[i] = 0.f; }
}

__global__ void count_edges_kernel(const int* __restrict__ idx, int E) {
    int e = blockIdx.x * blockDim.x + threadIdx.x;
    if (e < E) atomicAdd(&g_cnt[load_col(idx, e, E)], 1);
}

// phase 1: block-local exclusive scan of counts (256/block), emit block sums.
__global__ void scan1_kernel(int N) {
    __shared__ int sm[256];
    int t = threadIdx.x;
    int i = blockIdx.x * 256 + t;
    int c = (i < N) ? g_cnt[i] : 0;
    if (i < N) g_dinv[i] = rsqrtf((float)(c + 1));
    sm[t] = c;
    __syncthreads();
    int acc = c;
#pragma unroll
    for (int off = 1; off < 256; off <<= 1) {
        int v = (t >= off) ? sm[t - off] : 0;
        __syncthreads();
        acc += v;
        sm[t] = acc;
        __syncthreads();
    }
    if (i < N) g_start[i] = acc - c;           // exclusive
    if (t == 255) g_bsum[blockIdx.x] = acc;    // block total
}

// phase 2: single-block scan of block sums -> block offsets; writes g_start[N]
__global__ void scan2_kernel(int NB, int N) {
    __shared__ int sm[SCAN_NB_MAX];
    int t = threadIdx.x;
    int v = (t < NB) ? g_bsum[t] : 0;
    sm[t] = v;
    __syncthreads();
    int acc = v;
#pragma unroll
    for (int off = 1; off < SCAN_NB_MAX; off <<= 1) {
        int u = (t >= off) ? sm[t - off] : 0;
        __syncthreads();
        acc += u;
        sm[t] = acc;
        __syncthreads();
    }
    if (t < NB) g_boff[t] = acc - v;           // exclusive
    if (t == NB - 1) g_start[N] = acc;         // grand total = E
}

// phase 3: add block offsets
__global__ void scan3_kernel(int N) {
    int i = blockIdx.x * 256 + threadIdx.x;
    if (i < N) g_start[i] += g_boff[blockIdx.x];
}

__global__ void scatter_edges_kernel(const int* __restrict__ idx, int E) {
    int e = blockIdx.x * blockDim.x + threadIdx.x;
    if (e < E) {
        int r = load_row(idx, e);
        int c = load_col(idx, e, E);
        int p = g_start[c] + atomicAdd(&g_fill[c], 1);
        g_src[p] = r;
    }
}

// ---------------------------------------------------------------------------
// 2) TF32 tensor-core GEMM, N fixed = 96.  C = A[M,K] @ B[K,96]
//    BM=64 BN=96 BK=16, 256 threads (8 warps: 4m x 2n, 16x48 per warp).
//    Fused epilogue: bias / blend / relu / BN stats / xs prescale.
// ---------------------------------------------------------------------------
#define GBM 64
#define GBK 16
#define ALD 20    // As leading dim (floats), multiple of 4
#define BLD 100   // Bs / Csm leading dim (floats), multiple of 4

__global__ void __launch_bounds__(256) gemm_tf32_kernel(
    const float* __restrict__ A, const float* __restrict__ B,
    const float* __restrict__ bias, const float* __restrict__ blend,
    float ba, float bb, int do_relu, int write_xs, int stat_layer,
    float* __restrict__ out, int M, int K)
{
    __shared__ union SmU {
        struct { float As[GBM][ALD]; float Bs[GBK][BLD]; } ld;
        float Csm[GBM][BLD];
    } sm;
    __shared__ float RedS[8][96];
    __shared__ float RedQ[8][96];

    int tid = threadIdx.x;
    int w = tid >> 5;
    int wm = w >> 1;          // 0..3 : 16-row slab
    int wn = w & 1;           // 0..1 : 48-col slab
    int bm = blockIdx.x * GBM;

    wmma::fragment<wmma::accumulator, 16, 16, 8, float> c[3];
#pragma unroll
    for (int t = 0; t < 3; t++) wmma::fill_fragment(c[t], 0.f);

    // A load mapping: 64x16 floats = 256 float4, one per thread
    int arow = tid >> 2;          // 0..63
    int aq   = (tid & 3) * 4;     // 0,4,8,12

    for (int k0 = 0; k0 < K; k0 += GBK) {
        float4 av = make_float4(0.f, 0.f, 0.f, 0.f);
        int gr = bm + arow;
        if (gr < M) av = *(const float4*)(A + (size_t)gr * K + k0 + aq);
        sm.ld.As[arow][aq + 0] = wmma::__float_to_tf32(av.x);
        sm.ld.As[arow][aq + 1] = wmma::__float_to_tf32(av.y);
        sm.ld.As[arow][aq + 2] = wmma::__float_to_tf32(av.z);
        sm.ld.As[arow][aq + 3] = wmma::__float_to_tf32(av.w);
#pragma unroll
        for (int j = 0; j < 6; j++) {
            int i = tid + j * 256;          // 0..1535
            int bk = i / 96, bn = i - bk * 96;
            sm.ld.Bs[bk][bn] = wmma::__float_to_tf32(B[(size_t)(k0 + bk) * 96 + bn]);
        }
        __syncthreads();
#pragma unroll
        for (int kk = 0; kk < 2; kk++) {
            wmma::fragment<wmma::matrix_a, 16, 16, 8, wmma::precision::tf32, wmma::row_major> a;
            wmma::load_matrix_sync(a, &sm.ld.As[wm * 16][kk * 8], ALD);
#pragma unroll
            for (int t = 0; t < 3; t++) {
                wmma::fragment<wmma::matrix_b, 16, 16, 8, wmma::precision::tf32, wmma::row_major> b;
                wmma::load_matrix_sync(b, &sm.ld.Bs[kk * 8][wn * 48 + t * 16], BLD);
                wmma::mma_sync(c[t], a, b, c[t]);
            }
        }
        __syncthreads();
    }

    // stage accumulators to smem (union reuse; k-loop ended with sync)
#pragma unroll
    for (int t = 0; t < 3; t++)
        wmma::store_matrix_sync(&sm.Csm[wm * 16][wn * 48 + t * 16], c[t], BLD,
                                wmma::mem_row_major);
    __syncthreads();

    // epilogue: 8x32 thread grid; ty owns rows ty*8..ty*8+7, cols tx+{0,32,64}
    int tx = tid & 31, ty = tid >> 5;
    float s_c[3] = {0.f, 0.f, 0.f};
    float q_c[3] = {0.f, 0.f, 0.f};
#pragma unroll
    for (int rr = 0; rr < 8; rr++) {
        int row = bm + ty * 8 + rr;
        if (row >= M) continue;
        float dv = write_xs ? g_dinv[row] : 0.f;
#pragma unroll
        for (int j = 0; j < 3; j++) {
            int col = tx + j * 32;
            float v = sm.Csm[ty * 8 + rr][col];
            if (bias)  v += bias[col];
            if (blend) v = ba * blend[(size_t)row * 96 + col] + bb * v;
            if (do_relu) v = fmaxf(v, 0.f);
            size_t o = (size_t)row * 96 + col;
            out[o] = v;
            if (write_xs) g_xs[o] = dv * v;
            if (stat_layer >= 0) { s_c[j] += v; q_c[j] += v * v; }
        }
    }

    if (stat_layer >= 0) {
#pragma unroll
        for (int j = 0; j < 3; j++) {
            RedS[ty][tx + j * 32] = s_c[j];
            RedQ[ty][tx + j * 32] = q_c[j];
        }
        __syncthreads();
        if (ty == 0) {
#pragma unroll
            for (int j = 0; j < 3; j++) {
                int col = tx + j * 32;
                float s = 0.f, q = 0.f;
#pragma unroll
                for (int y = 0; y < 8; y++) { s += RedS[y][col]; q += RedQ[y][col]; }
                atomicAdd(&g_sum[stat_layer * H_DIM + col], s);
                atomicAdd(&g_sumsq[stat_layer * H_DIM + col], q);
            }
        }
    }
}

// ---------------------------------------------------------------------------
// 3) gather SpMM: one warp per destination node, 3 features/lane.
//    hp[c] = 0.9 * dinv[c] * (xs[c] + sum_{src} xs[src]) + 0.1 * x0[c]
// ---------------------------------------------------------------------------
__global__ void __launch_bounds__(256) gather_kernel(
    const float* __restrict__ xs, const float* __restrict__ x0,
    float* __restrict__ hp, int N)
{
    int warp = (blockIdx.x * blockDim.x + threadIdx.x) >> 5;
    int lane = threadIdx.x & 31;
    if (warp >= N) return;
    int c = warp;
    int s0 = g_start[c], s1 = g_start[c + 1];
    size_t base = (size_t)c * 96 + lane;
    float a0 = xs[base], a1 = xs[base + 32], a2 = xs[base + 64];
    int j = s0;
    for (; j + 1 < s1; j += 2) {          // unroll 2 for MLP
        int sA = g_src[j], sB = g_src[j + 1];
        const float* pA = xs + (size_t)sA * 96;
        const float* pB = xs + (size_t)sB * 96;
        a0 += pA[lane]      + pB[lane];
        a1 += pA[lane + 32] + pB[lane + 32];
        a2 += pA[lane + 64] + pB[lane + 64];
    }
    if (j < s1) {
        const float* p = xs + (size_t)g_src[j] * 96;
        a0 += p[lane]; a1 += p[lane + 32]; a2 += p[lane + 64];
    }
    float w = 0.9f * g_dinv[c];
    hp[base]      = w * a0 + 0.1f * x0[base];
    hp[base + 32] = w * a1 + 0.1f * x0[base + 32];
    hp[base + 64] = w * a2 + 0.1f * x0[base + 64];
}

// ---------------------------------------------------------------------------
// 4) BN apply + relu (+ prescale xs for next gather)
// ---------------------------------------------------------------------------
__global__ void __launch_bounds__(256) bn_apply_kernel(
    const float* __restrict__ h2, const float* __restrict__ gamma,
    const float* __restrict__ beta, int layer, float* __restrict__ x, int N)
{
    __shared__ float sc[96], sh[96];
    if (threadIdx.x < 96) {
        int h = threadIdx.x;
        float m  = g_sum[layer * H_DIM + h] / (float)N;
        float vr = g_sumsq[layer * H_DIM + h] / (float)N - m * m;
        float rs = rsqrtf(vr + 1e-5f);
        float s = gamma[h] * rs;
        sc[h] = s;
        sh[h] = beta[h] - m * s;
    }
    __syncthreads();
    int i = blockIdx.x * blockDim.x + threadIdx.x;
    int total = N * 96;
    if (i < total) {
        int h = i % 96;
        int r = i / 96;
        float v = sc[h] * h2[i] + sh[h];
        v = fmaxf(v, 0.f);
        x[i] = v;
        g_xs[i] = g_dinv[r] * v;
    }
}

// ---------------------------------------------------------------------------
// 5) fc2: out[M,40] = relu(BN(A))[M,96] @ W[96,40] + b   (BN fused, layer 2)
// ---------------------------------------------------------------------------
__global__ void __launch_bounds__(320) fc2_kernel(
    const float* __restrict__ A, const float* __restrict__ W,
    const float* __restrict__ bias, const float* __restrict__ gamma,
    const float* __restrict__ beta, int layer, float* __restrict__ out, int M)
{
    __shared__ float Ws[96 * 40];
    __shared__ float bs[40];
    __shared__ float Asm[8][96];
    __shared__ float sc[96], sh[96];
    int tid = threadIdx.x;
    for (int i = tid; i < 96 * 40; i += 320) Ws[i] = W[i];
    if (tid < 40) bs[tid] = bias[tid];
    if (tid < 96) {
        int h = tid;
        float m  = g_sum[layer * H_DIM + h] / (float)M;
        float vr = g_sumsq[layer * H_DIM + h] / (float)M - m * m;
        float rs = rsqrtf(vr + 1e-5f);
        float s = gamma[h] * rs;
        sc[h] = s;
        sh[h] = beta[h] - m * s;
    }
    int tx = tid % 40, ty = tid / 40;
    for (int r0 = blockIdx.x * 8; r0 < M; r0 += gridDim.x * 8) {
        __syncthreads();
        for (int i = tid; i < 768; i += 320) {
            int r = i / 96, k = i - r * 96;
            float v = (r0 + r < M) ? A[(size_t)(r0 + r) * 96 + k] : 0.f;
            v = fmaxf(sc[k] * v + sh[k], 0.f);   // BN + ReLU fused
            Asm[r][k] = v;
        }
        __syncthreads();
        float acc = bs[tx];
#pragma unroll
        for (int k = 0; k < 96; k++) acc += Asm[ty][k] * Ws[k * 40 + tx];
        if (r0 + ty < M) out[(size_t)(r0 + ty) * 40 + tx] = acc;
    }
}

// ---------------------------------------------------------------------------
// launch
// ---------------------------------------------------------------------------
extern "C" void kernel_launch(void* const* d_in, const int* in_sizes, int n_in,
                              void* d_out, int out_size) {
    const float* x_in    = (const float*)d_in[0];
    const int*   eidx    = (const int*)d_in[1];
    const float* fc1_w   = (const float*)d_in[2];
    const float* fc1_b   = (const float*)d_in[3];
    const float* conv_w  = (const float*)d_in[4];
    const float* bn_g    = (const float*)d_in[5];
    const float* bn_b    = (const float*)d_in[6];
    const float* fc2_w   = (const float*)d_in[7];
    const float* fc2_b   = (const float*)d_in[8];
    float* out = (float*)d_out;

    int N = in_sizes[0] / IN_DIM;   // 50000
    int E = in_sizes[1] / 2;        // 800000
    if (N > N_NODES) N = N_NODES;
    if (E > E_EDGES) E = E_EDGES;
    int NB = (N + 255) / 256;       // 196

    float *p_x0, *p_xs, *p_hp, *p_h2, *p_x;
    cudaGetSymbolAddress((void**)&p_x0, g_x0);
    cudaGetSymbolAddress((void**)&p_xs, g_xs);
    cudaGetSymbolAddress((void**)&p_hp, g_hp);
    cudaGetSymbolAddress((void**)&p_h2, g_h2);
    cudaGetSymbolAddress((void**)&p_x,  g_xcur);

    // ---- graph preprocessing (CSR + dinv) ----
    detect_idx_kernel<<<1, 512>>>(eidx, 2 * E);
    zero_all_kernel<<<NB, 256>>>(N);
    count_edges_kernel<<<(E + 255) / 256, 256>>>(eidx, E);
    scan1_kernel<<<NB, 256>>>(N);
    scan2_kernel<<<1, SCAN_NB_MAX>>>(NB, N);
    scan3_kernel<<<NB, 256>>>(N);
    scatter_edges_kernel<<<(E + 255) / 256, 256>>>(eidx, E);

    int gemm_grid = (N + GBM - 1) / GBM;

    // ---- fc1 + relu (writes x0 and xs = dinv*x0) ----
    gemm_tf32_kernel<<<gemm_grid, 256>>>(
        x_in, fc1_w, fc1_b, nullptr, 0.f, 0.f, /*relu=*/1, /*write_xs=*/1,
        /*stat_layer=*/-1, p_x0, N, IN_DIM);

    int gather_grid = (N * 32 + 255) / 256;
    int ew_grid = (N * 96 + 255) / 256;

    for (int i = 0; i < 3; i++) {
        float beta = logf(0.5f / (float)(i + 1) + 1.0f);
        // gather: hp = 0.9*agg + 0.1*x0
        gather_kernel<<<gather_grid, 256>>>(p_xs, p_x0, p_hp, N);
        // identity mapping: h2 = (1-beta)*hp + beta*(hp @ W_i), BN stats fused
        gemm_tf32_kernel<<<gemm_grid, 256>>>(
            p_hp, conv_w + (size_t)i * H_DIM * H_DIM, nullptr, p_hp,
            1.f - beta, beta, /*relu=*/0, /*write_xs=*/0, /*stat_layer=*/i,
            p_h2, N, H_DIM);
        if (i < 2) {
            bn_apply_kernel<<<ew_grid, 256>>>(
                p_h2, bn_g + i * H_DIM, bn_b + i * H_DIM, i, p_x, N);
        }
    }

    // ---- fc2 with layer-2 BN+ReLU fused ----
    fc2_kernel<<<512, 320>>>(p_h2, fc2_w, fc2_b, bn_g + 2 * H_DIM,
                             bn_b + 2 * H_DIM, 2, out, N);
}